// round 17
// baseline (speedup 1.0000x reference)
#include <cuda_runtime.h>
#include <cuda_bf16.h>
#include <cstdint>

namespace {
constexpr int Bn = 32;
constexpr int Tn = 1024;
constexpr int M  = Bn * 1024;

constexpr int Lc = 8;
constexpr int Cc = Tn / Lc;         // 128

constexpr int SZ  = 512 * 512;      // fp32 elements per matrix
constexpr int SZW = 256 * 512;      // packed bf16x2 words per matrix
constexpr int WST = 20;             // smem row stride in words
constexpr int BUFW = 7680;          // Ah 2560 | Al 2560 | Bh 1280 | Bl 1280
constexpr int SMEM_BYTES = 2 * BUFW * 4;   // 61440
}

// ---------------------------------------------------------------------------
// Static device scratch
// ---------------------------------------------------------------------------
__device__ float    g_Rf[8 * SZ];       // R^1..R^8 fp32
__device__ uint32_t g_Rh[8 * SZW];      // R^1..R^8 B-style packed hi
__device__ uint32_t g_Rl[8 * SZW];
__device__ float    g_Sf[6 * SZ];       // S^2,S^4,S^8,S^16,S^32,S^64 (S = R^8)
__device__ uint32_t g_Sh[6 * SZW];
__device__ uint32_t g_Sl[6 * SZW];
__device__ uint32_t g_Wh[SZW];
__device__ uint32_t g_Wl[SZW];
__device__ float    g_V0[Cc * Bn * 512];   // 4096 x 512
__device__ float    g_V1[Cc * Bn * 512];
__device__ int      g_flagP[8][32];        // pass1 step/group counters
__device__ int      g_lflag[8];            // pass1 ladder counters
__device__ int      g_flagS[7][32];        // scan step/group counters
__device__ int      g_lflagS[8];           // scan ladder counters

// ---------------------------------------------------------------------------
// helpers
// ---------------------------------------------------------------------------
__device__ __forceinline__ uint32_t packbf(float a, float b) {
    uint32_t r;  // low half = a, high half = b
    asm("cvt.rn.bf16x2.f32 %0, %1, %2;" : "=r"(r) : "f"(b), "f"(a));
    return r;
}
__device__ __forceinline__ float lo_f(uint32_t p) { return __uint_as_float(p << 16); }
__device__ __forceinline__ float hi_f(uint32_t p) { return __uint_as_float(p & 0xFFFF0000u); }

__device__ __forceinline__ void mma16816(float* c, const uint32_t* a,
                                         uint32_t b0, uint32_t b1) {
    asm volatile(
        "mma.sync.aligned.m16n8k16.row.col.f32.bf16.bf16.f32 "
        "{%0,%1,%2,%3}, {%4,%5,%6,%7}, {%8,%9}, {%0,%1,%2,%3};"
        : "+f"(c[0]), "+f"(c[1]), "+f"(c[2]), "+f"(c[3])
        : "r"(a[0]), "r"(a[1]), "r"(a[2]), "r"(a[3]), "r"(b0), "r"(b1));
}

__device__ __forceinline__ void ldsm4(uint32_t& r0, uint32_t& r1,
                                      uint32_t& r2, uint32_t& r3, uint32_t addr) {
    asm volatile(
        "ldmatrix.sync.aligned.m8n8.x4.shared.b16 {%0,%1,%2,%3}, [%4];"
        : "=r"(r0), "=r"(r1), "=r"(r2), "=r"(r3) : "r"(addr));
}

__device__ __forceinline__ void spin_until(volatile int* p, int v) {
    while (*p < v) { __nanosleep(64); }
}

// ---------------------------------------------------------------------------
// Double-buffered HMMA core (fp32 A converted in-kernel, pre-packed B,
// ldmatrix fragment loads).
// ---------------------------------------------------------------------------
__device__ __forceinline__ void hmma_core_bb(const float* __restrict__ arow,
                                             const uint32_t* __restrict__ bh,
                                             const uint32_t* __restrict__ bl,
                                             float acc[2][4][4])
{
    extern __shared__ uint32_t sw[];
    const uint32_t sb = (uint32_t)__cvta_generic_to_shared(sw);
    const int tid  = threadIdx.x;
    const int lane = tid & 31, wid = tid >> 5;
    const int mo = (wid >> 1) * 32, no = (wid & 1) * 32;

    const int sar = tid >> 1;
    const int saw = (tid & 1) * 8;
    const int sbw = (tid >> 6) * 4;

    const int aoffw = (lane & 15) * WST + (lane >> 4) * 4;
    const int jj = lane >> 3, iL = lane & 7;
    const int boffw = ((jj >> 1) * 8 + iL) * WST + (jj & 1) * 4;

    float af[16];
    uint32_t bhw[4], blw[4];

    auto LOAD = [&](int kc) {
        const float* ap = arow + kc * 32;
        float4 v;
        v = *(const float4*)(ap + 0);  af[0] = v.x;  af[1] = v.y;  af[2] = v.z;  af[3] = v.w;
        v = *(const float4*)(ap + 4);  af[4] = v.x;  af[5] = v.y;  af[6] = v.z;  af[7] = v.w;
        v = *(const float4*)(ap + 8);  af[8] = v.x;  af[9] = v.y;  af[10] = v.z; af[11] = v.w;
        v = *(const float4*)(ap + 12); af[12] = v.x; af[13] = v.y; af[14] = v.z; af[15] = v.w;
        const int off = (kc * 16 + sbw) * 512;
        bhw[0] = bh[off];        bhw[1] = bh[off + 512];
        bhw[2] = bh[off + 1024]; bhw[3] = bh[off + 1536];
        blw[0] = bl[off];        blw[1] = bl[off + 512];
        blw[2] = bl[off + 1024]; blw[3] = bl[off + 1536];
    };

    auto STORE = [&](int bi) {
        uint32_t h[8], l[8];
#pragma unroll
        for (int j = 0; j < 8; j++) {
            h[j] = packbf(af[2 * j], af[2 * j + 1]);
            l[j] = packbf(af[2 * j] - lo_f(h[j]), af[2 * j + 1] - hi_f(h[j]));
        }
        uint32_t* pA = sw + bi * BUFW + sar * WST + saw;
        *(uint4*)pA        = make_uint4(h[0], h[1], h[2], h[3]);
        *(uint4*)(pA + 4)  = make_uint4(h[4], h[5], h[6], h[7]);
        uint32_t* pAl = pA + 2560;
        *(uint4*)pAl       = make_uint4(l[0], l[1], l[2], l[3]);
        *(uint4*)(pAl + 4) = make_uint4(l[4], l[5], l[6], l[7]);
        uint32_t* pB = sw + bi * BUFW + 5120 + (tid & 63) * WST + sbw;
        *(uint4*)pB          = make_uint4(bhw[0], bhw[1], bhw[2], bhw[3]);
        *(uint4*)(pB + 1280) = make_uint4(blw[0], blw[1], blw[2], blw[3]);
    };

    auto COMPUTE = [&](int bi) {
        const uint32_t base = sb + (uint32_t)(bi * BUFW) * 4u;
#pragma unroll
        for (int s = 0; s < 2; s++) {
            const int ws = s * 8;
            uint32_t aH[2][4], aL[2][4];
#pragma unroll
            for (int mf = 0; mf < 2; mf++) {
                const uint32_t wa = base + (uint32_t)(((mo + mf * 16) * WST + ws + aoffw) * 4);
                ldsm4(aH[mf][0], aH[mf][1], aH[mf][2], aH[mf][3], wa);
                ldsm4(aL[mf][0], aL[mf][1], aL[mf][2], aL[mf][3], wa + 2560u * 4u);
            }
#pragma unroll
            for (int p = 0; p < 2; p++) {
                const uint32_t wb = base +
                    (uint32_t)((5120 + (no + p * 16) * WST + ws + boffw) * 4);
                uint32_t h0, h1, h2, h3, l0, l1, l2, l3;
                ldsm4(h0, h1, h2, h3, wb);
                ldsm4(l0, l1, l2, l3, wb + 1280u * 4u);
#pragma unroll
                for (int mf = 0; mf < 2; mf++) {
                    mma16816(acc[mf][2 * p],     aH[mf], h0, h1);
                    mma16816(acc[mf][2 * p],     aH[mf], l0, l1);
                    mma16816(acc[mf][2 * p],     aL[mf], h0, h1);
                    mma16816(acc[mf][2 * p + 1], aH[mf], h2, h3);
                    mma16816(acc[mf][2 * p + 1], aH[mf], l2, l3);
                    mma16816(acc[mf][2 * p + 1], aL[mf], h2, h3);
                }
            }
        }
    };

    LOAD(0); STORE(0); __syncthreads();
    int cur = 0;
    for (int kc = 0; kc < 16; kc++) {
        if (kc < 15) LOAD(kc + 1);
        COMPUTE(cur);
        if (kc < 15) { STORE(cur ^ 1); __syncthreads(); cur ^= 1; }
    }
}

// ladder epilogue: fp32 C + B-style packed (row-pair shuffle)
__device__ __forceinline__ void ladder_epilogue(
    const float acc[2][4][4], int mrow, int bn,
    float* __restrict__ Cz, uint32_t* __restrict__ Dh, uint32_t* __restrict__ Dl)
{
    const int tid = threadIdx.x;
    const int lane = tid & 31, wid = tid >> 5;
    const int g = lane >> 2, qi = lane & 3;
    const int mo = (wid >> 1) * 32, no = (wid & 1) * 32;
#pragma unroll
    for (int mf = 0; mf < 2; mf++)
#pragma unroll
        for (int f = 0; f < 4; f++) {
            const int r0  = mrow + mo + mf * 16 + g;
            const int col = bn + no + f * 8 + 2 * qi;
            *(float2*)(Cz + (size_t)r0 * 512 + col) =
                make_float2(acc[mf][f][0], acc[mf][f][1]);
            *(float2*)(Cz + (size_t)(r0 + 8) * 512 + col) =
                make_float2(acc[mf][f][2], acc[mf][f][3]);

            float pc0 = __shfl_sync(0xffffffffu, acc[mf][f][0], (lane + 4) & 31);
            float pc1 = __shfl_sync(0xffffffffu, acc[mf][f][1], (lane + 4) & 31);
            float pc2 = __shfl_sync(0xffffffffu, acc[mf][f][2], (lane + 4) & 31);
            float pc3 = __shfl_sync(0xffffffffu, acc[mf][f][3], (lane + 4) & 31);
            if ((g & 1) == 0) {
                const int w0 = r0 >> 1;
                const int w1 = (r0 + 8) >> 1;
                uint32_t h0 = packbf(acc[mf][f][0], pc0);
                Dh[(size_t)w0 * 512 + col] = h0;
                Dl[(size_t)w0 * 512 + col] =
                    packbf(acc[mf][f][0] - lo_f(h0), pc0 - hi_f(h0));
                uint32_t h1 = packbf(acc[mf][f][1], pc1);
                Dh[(size_t)w0 * 512 + col + 1] = h1;
                Dl[(size_t)w0 * 512 + col + 1] =
                    packbf(acc[mf][f][1] - lo_f(h1), pc1 - hi_f(h1));
                uint32_t h2 = packbf(acc[mf][f][2], pc2);
                Dh[(size_t)w1 * 512 + col] = h2;
                Dl[(size_t)w1 * 512 + col] =
                    packbf(acc[mf][f][2] - lo_f(h2), pc2 - hi_f(h2));
                uint32_t h3 = packbf(acc[mf][f][3], pc3);
                Dh[(size_t)w1 * 512 + col + 1] = h3;
                Dl[(size_t)w1 * 512 + col + 1] =
                    packbf(acc[mf][f][3] - lo_f(h3), pc3 - hi_f(h3));
            }
        }
}

// ---------------------------------------------------------------------------
// generic C = A @ B (fp32 out).  grid (n/64, m/128).  Used for XW.
// ---------------------------------------------------------------------------
__global__ __launch_bounds__(256, 2) void hmma_gemm_bb(
    const float* __restrict__ A, const uint32_t* __restrict__ Bh,
    const uint32_t* __restrict__ Bl, float* __restrict__ C)
{
    const int bn = blockIdx.x * 64;
    const int bm = blockIdx.y * 128;
    const int tid = threadIdx.x;
    const float* arow = A + (size_t)(bm + (tid >> 1)) * 512 + (tid & 1) * 16;
    float acc[2][4][4] = {};
    hmma_core_bb(arow, Bh + bn + (tid & 63), Bl + bn + (tid & 63), acc);

    const int lane = tid & 31, wid = tid >> 5;
    const int g = lane >> 2, qi = lane & 3;
    const int mo = (wid >> 1) * 32, no = (wid & 1) * 32;
#pragma unroll
    for (int mf = 0; mf < 2; mf++)
#pragma unroll
        for (int f = 0; f < 4; f++) {
            const int r0  = bm + mo + mf * 16 + g;
            const int col = bn + no + f * 8 + 2 * qi;
            *(float2*)(C + (size_t)r0 * 512 + col) =
                make_float2(acc[mf][f][0], acc[mf][f][1]);
            *(float2*)(C + (size_t)(r0 + 8) * 512 + col) =
                make_float2(acc[mf][f][2], acc[mf][f][3]);
        }
}

// ---------------------------------------------------------------------------
// Persistent pass1 (round 16, unchanged): grid (8, 36), loops t = 1..7.
// ---------------------------------------------------------------------------
__global__ __launch_bounds__(256, 2) void pass1_persist_kernel(
    const uint32_t* __restrict__ Rh, const uint32_t* __restrict__ Rl,
    float* __restrict__ O, float* __restrict__ V0,
    float* Rfb, uint32_t* Rhb, uint32_t* Rlb)
{
    const int bn  = blockIdx.x * 64;
    const int y   = blockIdx.y;
    const int tid = threadIdx.x;
    const bool isPass = (y < 32);

    const int aslot[8] = {0, 0, 0, 1, 0, 1, 2, 3};
    const int bslot[8] = {0, 0, 1, 1, 3, 3, 3, 3};

    for (int t = 1; t < Lc; t++) {
        if (isPass) {
            if (t > 1) {
                if (tid == 0) spin_until(&g_flagP[t - 1][y], 8);
                __syncthreads();
                __threadfence();
            }
        } else {
            if (t > 1) {
                if (tid == 0) {
                    if (aslot[t] > 0) spin_until(&g_lflag[aslot[t]], 32);
                    if (bslot[t] > 0) spin_until(&g_lflag[bslot[t]], 32);
                }
                __syncthreads();
                __threadfence();
            }
        }

        if (isPass) {
            const int bm = y * 128;
            const int srow = bm + (tid >> 1);
            const float* arow = O + ((size_t)(srow & 31) * Tn + (size_t)(srow >> 5) * Lc + (t - 1)) * 512
                                + (tid & 1) * 16;
            float acc[2][4][4] = {};
            hmma_core_bb(arow, Rh + bn + (tid & 63), Rl + bn + (tid & 63), acc);

            const int lane = tid & 31, wid = tid >> 5;
            const int g = lane >> 2, qi = lane & 3;
            const int mo = (wid >> 1) * 32, no = (wid & 1) * 32;
#pragma unroll
            for (int mf = 0; mf < 2; mf++)
#pragma unroll
                for (int f = 0; f < 4; f++) {
                    const int col = bn + no + f * 8 + 2 * qi;
#pragma unroll
                    for (int h = 0; h < 2; h++) {
                        const int r = bm + mo + mf * 16 + g + h * 8;
                        float* op = O + ((size_t)(r & 31) * Tn + (size_t)(r >> 5) * Lc + t) * 512 + col;
                        float2 e = *(float2*)op;
                        e.x += acc[mf][f][2 * h];
                        e.y += acc[mf][f][2 * h + 1];
                        *(float2*)op = e;
                        if (t == Lc - 1)
                            *(float2*)(V0 + (size_t)r * 512 + col) = e;
                    }
                }
        } else {
            const int mrow = (y - 32) * 128;
            const float*    LA  = Rfb + (size_t)aslot[t] * SZ;
            const uint32_t* LBh = Rhb + (size_t)bslot[t] * SZW;
            const uint32_t* LBl = Rlb + (size_t)bslot[t] * SZW;
            const float* arow = LA + (size_t)(mrow + (tid >> 1)) * 512 + (tid & 1) * 16;
            float acc[2][4][4] = {};
            hmma_core_bb(arow, LBh + bn + (tid & 63), LBl + bn + (tid & 63), acc);
            ladder_epilogue(acc, mrow, bn, Rfb + (size_t)t * SZ,
                            Rhb + (size_t)t * SZW, Rlb + (size_t)t * SZW);
        }

        __threadfence();
        __syncthreads();
        if (tid == 0) {
            if (isPass) atomicAdd(&g_flagP[t][y], 1);
            else        atomicAdd(&g_lflag[t], 1);
        }
    }
}

// ---------------------------------------------------------------------------
// Persistent scan + fused pass3: grid (8, 36).
//   y < 32:  scan steps i=0..6 (V0/V1 ping-pong, per-group flags), then
//            pass3 tiles t=0..7 for this row group (gated on flagS[6][y]==8).
//   y >= 32: S-power ladder slots 0..5, then exit.
// ---------------------------------------------------------------------------
__global__ __launch_bounds__(256, 2) void scan_persist_kernel(
    float* __restrict__ V0, float* __restrict__ V1, float* __restrict__ O,
    const uint32_t* __restrict__ Rh, const uint32_t* __restrict__ Rl,
    const float* __restrict__ Rf7,
    float* Sfb, uint32_t* Shb, uint32_t* Slb)
{
    const int bn  = blockIdx.x * 64;
    const int y   = blockIdx.y;
    const int tid = threadIdx.x;

    if (y < 32) {
        const int bm = y * 128;
        for (int i = 0; i < 7; i++) {
            const int d = 1 << i;
            if (i > 0) {
                if (tid == 0) {
                    spin_until(&g_flagS[i - 1][y], 8);
                    int gs = 4 * y - d;
                    gs = (gs >= 0) ? (gs >> 2) : 0;
                    if (gs != y) spin_until(&g_flagS[i - 1][gs], 8);
                    spin_until(&g_lflagS[i - 1], 32);
                }
                __syncthreads();
                __threadfence();
            }

            const float* Vin = (i & 1) ? V1 : V0;
            float* Vout = (i & 1) ? V0 : V1;
            const uint32_t* Sph = (i == 0) ? (Rh + (size_t)7 * SZW)
                                           : (Shb + (size_t)(i - 1) * SZW);
            const uint32_t* Spl = (i == 0) ? (Rl + (size_t)7 * SZW)
                                           : (Slb + (size_t)(i - 1) * SZW);

            const int srow = bm + (tid >> 1);
            const int csrc = (srow >> 5) - d;
            const int asrc = (csrc >= 0) ? (csrc * 32 + (srow & 31)) : srow;
            const float* arow = Vin + (size_t)asrc * 512 + (tid & 1) * 16;
            float acc[2][4][4] = {};
            hmma_core_bb(arow, Sph + bn + (tid & 63), Spl + bn + (tid & 63), acc);

            const int lane = tid & 31, wid = tid >> 5;
            const int g = lane >> 2, qi = lane & 3;
            const int mo = (wid >> 1) * 32, no = (wid & 1) * 32;
#pragma unroll
            for (int mf = 0; mf < 2; mf++)
#pragma unroll
                for (int f = 0; f < 4; f++) {
                    const int col = bn + no + f * 8 + 2 * qi;
#pragma unroll
                    for (int h = 0; h < 2; h++) {
                        const int r = bm + mo + mf * 16 + g + h * 8;
                        float2 e = *(const float2*)(Vin + (size_t)r * 512 + col);
                        if ((r >> 5) >= d) {
                            e.x += acc[mf][f][2 * h];
                            e.y += acc[mf][f][2 * h + 1];
                        }
                        *(float2*)(Vout + (size_t)r * 512 + col) = e;
                    }
                }

            __threadfence();
            __syncthreads();
            if (tid == 0) atomicAdd(&g_flagS[i][y], 1);
        }

        // ---- fused pass3: all 8 bn-writers of this group must be done ----
        if (tid == 0) spin_until(&g_flagS[6][y], 8);
        __syncthreads();
        __threadfence();

        for (int t = 0; t < 8; t++) {
            const int vr = bm + (tid >> 1);
            const float* arow = V1 + (size_t)vr * 512 + (tid & 1) * 16;   // final V
            float acc[2][4][4] = {};
            hmma_core_bb(arow, Rh + (size_t)t * SZW + bn + (tid & 63),
                         Rl + (size_t)t * SZW + bn + (tid & 63), acc);

            const int lane = tid & 31, wid = tid >> 5;
            const int g = lane >> 2, qi = lane & 3;
            const int mo = (wid >> 1) * 32, no = (wid & 1) * 32;
#pragma unroll
            for (int mf = 0; mf < 2; mf++)
#pragma unroll
                for (int f = 0; f < 4; f++) {
                    const int col = bn + no + f * 8 + 2 * qi;
#pragma unroll
                    for (int h = 0; h < 2; h++) {
                        const int r = bm + mo + mf * 16 + g + h * 8;
                        const int cidx = r >> 5;       // = c-1
                        if (cidx < Cc - 1) {
                            const int b = r & 31;
                            float* op = O + ((size_t)b * Tn + (size_t)(cidx + 1) * Lc + t) * 512 + col;
                            float2 e = *(float2*)op;
                            e.x += acc[mf][f][2 * h];
                            e.y += acc[mf][f][2 * h + 1];
                            *(float2*)op = e;
                        }
                    }
                }
        }
    } else {
        // ---- ladder: S^2..S^64 (slots 0..5) ----
        const int mrow = (y - 32) * 128;
        for (int i = 0; i < 6; i++) {
            if (i > 0) {
                if (tid == 0) spin_until(&g_lflagS[i - 1], 32);
                __syncthreads();
                __threadfence();
            }
            const float* LA = (i == 0) ? Rf7 : (Sfb + (size_t)(i - 1) * SZ);
            const uint32_t* LBh = (i == 0) ? (Rh + (size_t)7 * SZW)
                                           : (Shb + (size_t)(i - 1) * SZW);
            const uint32_t* LBl = (i == 0) ? (Rl + (size_t)7 * SZW)
                                           : (Slb + (size_t)(i - 1) * SZW);
            const float* arow = LA + (size_t)(mrow + (tid >> 1)) * 512 + (tid & 1) * 16;
            float acc[2][4][4] = {};
            hmma_core_bb(arow, LBh + bn + (tid & 63), LBl + bn + (tid & 63), acc);
            ladder_epilogue(acc, mrow, bn, Sfb + (size_t)i * SZ,
                            Shb + (size_t)i * SZW, Slb + (size_t)i * SZW);

            __threadfence();
            __syncthreads();
            if (tid == 0) atomicAdd(&g_lflagS[i], 1);
        }
    }
}

// ---------------------------------------------------------------------------
// Merged prologue: pack W / pack R / copy R->Rf / zero all flags.
// ---------------------------------------------------------------------------
__global__ void prologue_kernel(const float* __restrict__ w,
                                const float* __restrict__ r,
                                uint32_t* __restrict__ Wh, uint32_t* __restrict__ Wl,
                                uint32_t* __restrict__ Rh, uint32_t* __restrict__ Rl,
                                float* __restrict__ Rf)
{
    const int bid = blockIdx.x;
    if (bid == 0) {
        ((int*)g_flagP)[threadIdx.x] = 0;               // 256 ints
        if (threadIdx.x < 224) ((int*)g_flagS)[threadIdx.x] = 0;
        if (threadIdx.x < 8) { g_lflag[threadIdx.x] = 0; g_lflagS[threadIdx.x] = 0; }
    }
    if (bid < 1024) {
        const bool isW = bid < 512;
        const float* src = isW ? w : r;
        uint32_t* dh = isW ? Wh : Rh;
        uint32_t* dl = isW ? Wl : Rl;
        const int i = (isW ? bid : bid - 512) * 256 + threadIdx.x;
        const int ww = i >> 9, n = i & 511;
        const float* s = src + (size_t)(2 * ww) * 512 + n;
        const float s0 = s[0], s1 = s[512];
        const uint32_t h = packbf(s0, s1);
        dh[i] = h;
        dl[i] = packbf(s0 - lo_f(h), s1 - hi_f(h));
    } else {
        const int i = (bid - 1024) * 256 + threadIdx.x;
        ((float4*)Rf)[i] = ((const float4*)r)[i];
    }
}

// ---------------------------------------------------------------------------
// Launch sequence: 4 kernels total.
// ---------------------------------------------------------------------------
extern "C" void kernel_launch(void* const* d_in, const int* in_sizes, int n_in,
                              void* d_out, int out_size)
{
    const float* x = (const float*)d_in[0];
    const float* w = (const float*)d_in[1];
    const float* r = (const float*)d_in[2];
    float* o = (float*)d_out;
    (void)in_sizes; (void)n_in; (void)out_size;

    float *Rf, *Sf, *V0, *V1;
    uint32_t *Rh, *Rl, *Sh, *Sl, *Wh, *Wl;
    cudaGetSymbolAddress((void**)&Rf, g_Rf);
    cudaGetSymbolAddress((void**)&Rh, g_Rh);
    cudaGetSymbolAddress((void**)&Rl, g_Rl);
    cudaGetSymbolAddress((void**)&Sf, g_Sf);
    cudaGetSymbolAddress((void**)&Sh, g_Sh);
    cudaGetSymbolAddress((void**)&Sl, g_Sl);
    cudaGetSymbolAddress((void**)&Wh, g_Wh);
    cudaGetSymbolAddress((void**)&Wl, g_Wl);
    cudaGetSymbolAddress((void**)&V0, g_V0);
    cudaGetSymbolAddress((void**)&V1, g_V1);

    cudaFuncSetAttribute(hmma_gemm_bb,         cudaFuncAttributeMaxDynamicSharedMemorySize, SMEM_BYTES);
    cudaFuncSetAttribute(pass1_persist_kernel, cudaFuncAttributeMaxDynamicSharedMemorySize, SMEM_BYTES);
    cudaFuncSetAttribute(scan_persist_kernel,  cudaFuncAttributeMaxDynamicSharedMemorySize, SMEM_BYTES);

    // Prologue: pack W, pack R, seed Rf, zero flags.
    prologue_kernel<<<1280, 256>>>(w, r, Wh, Wl, Rh, Rl, Rf);

    // Phase A: O = X @ W
    hmma_gemm_bb<<<dim3(8, M / 128), 256, SMEM_BYTES>>>(x, Wh, Wl, o);

    // Phases C + B: persistent pass1 + R-power ladder.
    pass1_persist_kernel<<<dim3(8, 36), 256, SMEM_BYTES>>>(
        Rh, Rl, o, V0, Rf, Rh, Rl);

    // Phases D + E: persistent scan + S-power ladder + fused pass3.
    scan_persist_kernel<<<dim3(8, 36), 256, SMEM_BYTES>>>(
        V0, V1, o, Rh, Rl, Rf + (size_t)7 * SZ, Sf, Sh, Sl);
}